// round 5
// baseline (speedup 1.0000x reference)
#include <cuda_runtime.h>
#include <cuda_bf16.h>

#define NROWS  8192
#define DIM    1024
#define NPAIRS 1024
#define MARGIN_RANK 0.05f
#define FULL   0xFFFFFFFFu

// ---------------- device scratch (no allocations allowed) ----------------
__device__ float g_sp[NROWS];       // dp * rsqrt(|row|^2)  (row order, no text norm)
__device__ float g_sn[NROWS];       // dn * rsqrt(|row|^2)
__device__ int   g_ridx[NROWS];     // bucket-sorted slot -> row index
__device__ int   g_bcount[NPAIRS];
__device__ int   g_bstart[NPAIRS];
__device__ float g_invp, g_invn;    // text-vector inverse norms
__device__ float g_cons_sum, g_pos_sum, g_neg_sum;
__device__ int   g_cons_cnt, g_rank_cnt;
__device__ int   g_done;

// ---------------- K1: block 0 = prep, blocks 1..1024 = GEMV --------------
// The prep block (histogram/scan/index, ~few us on one SM) runs concurrently
// with the 1024 GEMV blocks that saturate HBM on the remaining SMs.
__global__ void __launch_bounds__(256) K1(
    const float4* __restrict__ x, const float* __restrict__ tp,
    const float* __restrict__ tn, const int* __restrict__ pair)
{
    __shared__ int            scnt[NPAIRS];    // histogram counts
    __shared__ int            sstart[NPAIRS];  // exclusive starts
    __shared__ unsigned short srank[NROWS];    // per-row rank within its bucket
    __shared__ int            wtot[8];
    __shared__ float          sA[8], sB[8];

    int t    = threadIdx.x;
    int lane = t & 31;
    int w    = t >> 5;

    if (blockIdx.x == 0) {
        // ---------------- prep path (256 threads) ----------------
        #pragma unroll
        for (int j = 0; j < 4; j++) scnt[t + j * 256] = 0;
        if (t == 0) {
            g_cons_sum = 0.f; g_pos_sum = 0.f; g_neg_sum = 0.f;
            g_cons_cnt = 0;   g_rank_cnt = 0;  g_done = 0;
        }

        // text-vector inverse norms
        float pa = 0.f, pb = 0.f;
        #pragma unroll
        for (int j = 0; j < 4; j++) {
            float a = tp[t + j * 256];
            float b = tn[t + j * 256];
            pa += a * a;  pb += b * b;
        }
        #pragma unroll
        for (int o = 16; o; o >>= 1) {
            pa += __shfl_xor_sync(FULL, pa, o);
            pb += __shfl_xor_sync(FULL, pb, o);
        }
        if (lane == 0) { sA[w] = pa; sB[w] = pb; }
        __syncthreads();
        if (t == 0) {
            float qa = 0.f, qb = 0.f;
            #pragma unroll
            for (int j = 0; j < 8; j++) { qa += sA[j]; qb += sB[j]; }
            g_invp = rsqrtf(qa);
            g_invn = rsqrtf(qb);
        }
        __syncthreads();

        // histogram with rank capture (shared atomics)
        #pragma unroll 8
        for (int j = 0; j < 32; j++) {
            int i = t + j * 256;
            srank[i] = (unsigned short)atomicAdd(&scnt[pair[i]], 1);
        }
        __syncthreads();

        // exclusive scan over 1024 counts; thread owns buckets 4t..4t+3
        int s0 = scnt[4 * t + 0], s1 = scnt[4 * t + 1];
        int s2 = scnt[4 * t + 2], s3 = scnt[4 * t + 3];
        int tot = s0 + s1 + s2 + s3;
        int inc = tot;
        #pragma unroll
        for (int o = 1; o < 32; o <<= 1) {
            int n = __shfl_up_sync(FULL, inc, o);
            if (lane >= o) inc += n;
        }
        if (lane == 31) wtot[w] = inc;
        __syncthreads();
        if (t == 0) {
            int acc = 0;
            #pragma unroll
            for (int j = 0; j < 8; j++) { int v = wtot[j]; wtot[j] = acc; acc += v; }
        }
        __syncthreads();
        int base = wtot[w] + inc - tot;       // exclusive base for bucket 4t
        sstart[4 * t + 0] = base;             g_bstart[4 * t + 0] = base;
        g_bcount[4 * t + 0] = s0;             base += s0;
        sstart[4 * t + 1] = base;             g_bstart[4 * t + 1] = base;
        g_bcount[4 * t + 1] = s1;             base += s1;
        sstart[4 * t + 2] = base;             g_bstart[4 * t + 2] = base;
        g_bcount[4 * t + 2] = s2;             base += s2;
        sstart[4 * t + 3] = base;             g_bstart[4 * t + 3] = base;
        g_bcount[4 * t + 3] = s3;
        __syncthreads();

        // scatter row indices into bucket-sorted slots
        #pragma unroll 8
        for (int j = 0; j < 32; j++) {
            int i = t + j * 256;
            g_ridx[sstart[pair[i]] + (int)srank[i]] = i;
        }
    } else {
        // ---------------- GEMV path: one warp per row ----------------
        int row  = (blockIdx.x - 1) * 8 + w;
        const float4* r4  = x + (size_t)row * (DIM / 4);
        const float4* tp4 = (const float4*)tp;
        const float4* tn4 = (const float4*)tn;

        // 8 independent row loads in flight
        float4 v[8];
        #pragma unroll
        for (int k = 0; k < 8; k++) v[k] = r4[k * 32 + lane];

        float dp = 0.f, dn = 0.f, dx = 0.f;
        #pragma unroll
        for (int k = 0; k < 8; k++) {
            float4 p = __ldg(tp4 + k * 32 + lane);   // L1-resident after first touch
            float4 q = __ldg(tn4 + k * 32 + lane);
            dp += v[k].x*p.x + v[k].y*p.y + v[k].z*p.z + v[k].w*p.w;
            dn += v[k].x*q.x + v[k].y*q.y + v[k].z*q.z + v[k].w*q.w;
            dx += v[k].x*v[k].x + v[k].y*v[k].y + v[k].z*v[k].z + v[k].w*v[k].w;
        }
        #pragma unroll
        for (int o = 16; o; o >>= 1) {
            dp += __shfl_xor_sync(FULL, dp, o);
            dn += __shfl_xor_sync(FULL, dn, o);
            dx += __shfl_xor_sync(FULL, dx, o);
        }
        if (lane == 0) {
            float inv = rsqrtf(dx);
            g_sp[row] = dp * inv;
            g_sn[row] = dn * inv;
        }
    }
}

// ---------------- K2: shuffle all-pairs per bucket + fused finalize -------
__global__ void __launch_bounds__(256) K2_pairs(const int* __restrict__ lev,
                                                float* __restrict__ out) {
    int wg   = (blockIdx.x * 256 + threadIdx.x) >> 5;  // bucket id
    int lane = threadIdx.x & 31;
    int start = g_bstart[wg];
    int c     = g_bcount[wg];
    float invp = g_invp, invn = g_invn;

    float cs = 0.f, ps = 0.f, ns = 0.f;
    int cc = 0, rc = 0;

    if (c <= 32) {
        // one element per lane; gather through g_ridx, then pure shuffles
        float sp = 0.f, sn = 0.f; int lv = 0;
        bool act = lane < c;
        if (act) {
            int r = g_ridx[start + lane];
            sp = g_sp[r] * invp;
            sn = g_sn[r] * invn;
            lv = lev[r];
        }
        for (int b = 0; b < c; b++) {
            float spb = __shfl_sync(FULL, sp, b);
            float snb = __shfl_sync(FULL, sn, b);
            int   lb  = __shfl_sync(FULL, lv, b);
            if (act && lv == lb && lane < b) {
                cs += fabsf(sp - spb) + fabsf(sn - snb);
                cc++;
            }
            if (act && lv < lb) {
                ps += fmaxf(MARGIN_RANK - (sp - spb), 0.f);
                ns += fmaxf(MARGIN_RANK + (sn - snb), 0.f);
                rc++;
            }
        }
    } else {
        // fallback for improbable large buckets
        for (int a = lane; a < c; a += 32) {
            int ra = g_ridx[start + a];
            float spa = g_sp[ra] * invp;
            float sna = g_sn[ra] * invn;
            int   la  = lev[ra];
            for (int b = 0; b < c; b++) {
                int rb = g_ridx[start + b];
                float spb = g_sp[rb] * invp;
                float snb = g_sn[rb] * invn;
                int   lb  = lev[rb];
                if (la == lb && a < b) {
                    cs += fabsf(spa - spb) + fabsf(sna - snb);
                    cc++;
                }
                if (la < lb) {
                    ps += fmaxf(MARGIN_RANK - (spa - spb), 0.f);
                    ns += fmaxf(MARGIN_RANK + (sna - snb), 0.f);
                    rc++;
                }
            }
        }
    }

    #pragma unroll
    for (int o = 16; o; o >>= 1) {
        cs += __shfl_xor_sync(FULL, cs, o);
        ps += __shfl_xor_sync(FULL, ps, o);
        ns += __shfl_xor_sync(FULL, ns, o);
        cc += __shfl_xor_sync(FULL, cc, o);
        rc += __shfl_xor_sync(FULL, rc, o);
    }
    if (lane == 0 && (cc | rc)) {
        atomicAdd(&g_cons_sum, cs);
        atomicAdd(&g_pos_sum,  ps);
        atomicAdd(&g_neg_sum,  ns);
        atomicAdd(&g_cons_cnt, cc);
        atomicAdd(&g_rank_cnt, rc);
    }

    // fused finalize: last block writes the scalar
    __syncthreads();
    if (threadIdx.x == 0) {
        __threadfence();
        if (atomicAdd(&g_done, 1) == (int)gridDim.x - 1) {
            __threadfence();
            float lc = (g_cons_cnt > 0) ? g_cons_sum / (float)(2 * g_cons_cnt) : 0.f;
            float lp = (g_rank_cnt > 0) ? g_pos_sum  / (float)g_rank_cnt       : 0.f;
            float ln = (g_rank_cnt > 0) ? g_neg_sum  / (float)g_rank_cnt       : 0.f;
            out[0] = lc + lp + ln;
        }
    }
}

// ---------------- launch ---------------------------------------------------
extern "C" void kernel_launch(void* const* d_in, const int* in_sizes, int n_in,
                              void* d_out, int out_size) {
    const float* img  = (const float*)d_in[0];  // [8192, 1024]
    const float* tp   = (const float*)d_in[1];  // [1024]
    const float* tn   = (const float*)d_in[2];  // [1024]
    const int*   lev  = (const int*)  d_in[3];  // [8192]
    const int*   pair = (const int*)  d_in[4];  // [8192]
    float* out = (float*)d_out;

    K1<<<1 + NROWS / 8, 256>>>((const float4*)img, tp, tn, pair);
    K2_pairs<<<(NPAIRS * 32) / 256, 256>>>(lev, out);
}